// round 1
// baseline (speedup 1.0000x reference)
#include <cuda_runtime.h>
#include <math.h>

// Problem dims
constexpr int nB = 128;   // batch
constexpr int nS = 128;   // seq
constexpr int nW = 16;    // window
constexpr int nV = 128;   // vocab
constexpr int nH = 512;   // hidden
constexpr int nL = 64;    // out features
constexpr int nG = 3 * nH; // 1536 gates

// ---- scratch (device globals; no allocations allowed) ----
__device__ float g_x[nB * nS * nV];            // FOFE encodings [b][s][v]   (8 MB)
__device__ float g_WT[2][nV * nG];             // transposed W_ih  [d][v][g] (1.5 MB)
__device__ float g_xw[2ull * nS * nB * nG];    // input projections [d][s][b][g] (201 MB)
__device__ float g_ys[2ull * nB * nS * nH];    // GRU outputs [d][b][s][i] (67 MB)
__device__ float g_h[2][2][nB * nH];           // hidden double buffer [parity][d][b*H+i]

// ============================================================
// 1) FOFE: one warp per (b,s). x[b,s,v] = sum_w wt[w]*[chars[w]==v]
//    wt[w] = (c!=0) * forget^(# nonzero chars strictly after w)
// ============================================================
__global__ void fofe_kernel(const int* __restrict__ chars,
                            const float* __restrict__ forget_p) {
    int warp = (blockIdx.x * blockDim.x + threadIdx.x) >> 5;
    if (warp >= nB * nS) return;
    int lane = threadIdx.x & 31;
    const int* cp = chars + (size_t)warp * nW;
    int c = 0;
    if (lane < nW) c = cp[lane];
    bool nz = (lane < nW) && (c != 0);
    unsigned ball = __ballot_sync(0xffffffffu, nz);
    float wt = 0.f;
    if (nz) {
        int cnt = __popc(ball & (0xFFFFFFFEu << lane)); // bits strictly above lane
        wt = powf(*forget_p, (float)cnt);
    }
    float a0 = 0.f, a1 = 0.f, a2 = 0.f, a3 = 0.f; // vocab slots lane*4 .. +3
#pragma unroll
    for (int w = 0; w < nW; w++) {
        int cw = __shfl_sync(0xffffffffu, c, w);
        float ww = __shfl_sync(0xffffffffu, wt, w);
        int dd = cw - lane * 4;
        if (dd == 0) a0 += ww;
        else if (dd == 1) a1 += ww;
        else if (dd == 2) a2 += ww;
        else if (dd == 3) a3 += ww;
    }
    *(float4*)&g_x[(size_t)warp * nV + lane * 4] = make_float4(a0, a1, a2, a3);
}

// ============================================================
// 2) Transpose W_ih (g,v) -> (v,g) for coalesced GEMM loads
// ============================================================
__global__ void wt_kernel(const float* __restrict__ Wf,
                          const float* __restrict__ Wb) {
    int idx = blockIdx.x * 256 + threadIdx.x;
    if (idx >= 2 * nV * nG) return;
    int d = idx / (nV * nG);
    int rem = idx - d * (nV * nG);
    int v = rem / nG, g = rem - v * nG;
    const float* Wsrc = d ? Wb : Wf;
    g_WT[d][rem] = Wsrc[g * nV + v];
}

// ============================================================
// 3) Input GEMM: xw[d][s][b][g] = b_ih[g] + sum_v x[b][s][v] * W_ih[g][v]
//    rows r = b*nS + s (x's natural order). Tile 64 rows x 32 cols, K=128.
// ============================================================
__global__ void __launch_bounds__(256) xw_kernel(const float* __restrict__ bihf,
                                                 const float* __restrict__ bihb) {
    int d = blockIdx.z;
    int r0 = blockIdx.x * 64;
    int g0 = blockIdx.y * 32;
    __shared__ float xs[64][nV];   // [row][k]  32 KB
    __shared__ float ws[nV][32];   // [k][col]  16 KB
    int tid = threadIdx.x;
    // load x tile (coalesced float4)
    for (int p = tid; p < 64 * 32; p += 256) {
        int rr = p >> 5, k4 = p & 31;
        *(float4*)&xs[rr][k4 * 4] =
            *(const float4*)&g_x[(size_t)(r0 + rr) * nV + k4 * 4];
    }
    // load W tile from transposed layout (coalesced)
    const float* WT = g_WT[d];
    for (int p = tid; p < nV * 8; p += 256) {
        int v = p >> 3, c4 = p & 7;
        float4 w = *(const float4*)&WT[(size_t)v * nG + g0 + c4 * 4];
        ws[v][c4 * 4 + 0] = w.x; ws[v][c4 * 4 + 1] = w.y;
        ws[v][c4 * 4 + 2] = w.z; ws[v][c4 * 4 + 3] = w.w;
    }
    __syncthreads();
    int col = tid & 31, rg = tid >> 5;
    float acc[8] = {0, 0, 0, 0, 0, 0, 0, 0};
#pragma unroll 4
    for (int k = 0; k < nV; k++) {
        float w = ws[k][col];
#pragma unroll
        for (int j = 0; j < 8; j++) acc[j] += xs[rg * 8 + j][k] * w;
    }
    const float* bp = d ? bihb : bihf;
    float bias = bp[g0 + col];
#pragma unroll
    for (int j = 0; j < 8; j++) {
        int r = r0 + rg * 8 + j;
        int bi = r >> 7, si = r & 127;
        g_xw[(((size_t)d * nS + si) * nB + bi) * nG + g0 + col] = acc[j] + bias;
    }
}

// ============================================================
// 4) zero initial hidden state (parity 0 buffer, both dirs)
// ============================================================
__global__ void hzero_kernel() {
    int idx = blockIdx.x * 256 + threadIdx.x;
    float* p = &g_h[0][0][0];
    if (idx < 2 * nB * nH) p[idx] = 0.f;
}

// ============================================================
// 5) One GRU step, both directions. Grid: 128 blocks
//    block = (dir, i-chunk of 8 hidden units). Tile: 128 b x 8 i x 3 gates.
//    Thread (il = tid/32, lane): 4 batches (lane*4..+3) x 3 gates for i=i0+il.
// ============================================================
__global__ void __launch_bounds__(256) scan_kernel(
    int step, int par,
    const float* __restrict__ Whf, const float* __restrict__ bhf,
    const float* __restrict__ Whb, const float* __restrict__ bhb,
    const int* __restrict__ lengths) {
    int d = blockIdx.x >> 6;
    int ic = blockIdx.x & 63;
    int i0 = ic * 8;
    const float* Wh = d ? Whb : Whf;
    const float* bh = d ? bhb : bhf;
    const float* hin = g_h[par][d];
    float* hout = g_h[par ^ 1][d];

    __shared__ float hs[64][129];      // [k][b], pad 129 -> conflict-free scalar access
    __shared__ float wsm[3][8][64];    // [gate][il][k]

    int tid = threadIdx.x;
    int il = tid >> 5, lane = tid & 31;
    float aR[4] = {0, 0, 0, 0}, aZ[4] = {0, 0, 0, 0}, aN[4] = {0, 0, 0, 0};

    for (int kc = 0; kc < nH; kc += 64) {
        // stage h chunk: 128 b x 64 k (coalesced global, conflict-free smem store)
        for (int p = tid; p < 2048; p += 256) {
            int bidx = p >> 4, k4 = p & 15;
            float4 v = *(const float4*)&hin[(size_t)bidx * nH + kc + k4 * 4];
            int k = k4 * 4;
            hs[k + 0][bidx] = v.x; hs[k + 1][bidx] = v.y;
            hs[k + 2][bidx] = v.z; hs[k + 3][bidx] = v.w;
        }
        // stage 24 W rows x 64 k
        for (int p = tid; p < 384; p += 256) {
            int row = p >> 4, k4 = p & 15;
            int gate = row >> 3, rr = row & 7;
            float4 v = *(const float4*)&Wh[((size_t)gate * nH + i0 + rr) * nH + kc + k4 * 4];
            int k = k4 * 4;
            wsm[gate][rr][k + 0] = v.x; wsm[gate][rr][k + 1] = v.y;
            wsm[gate][rr][k + 2] = v.z; wsm[gate][rr][k + 3] = v.w;
        }
        __syncthreads();
#pragma unroll 8
        for (int k = 0; k < 64; k++) {
            float wr = wsm[0][il][k], wz = wsm[1][il][k], wn = wsm[2][il][k];
            float h0 = hs[k][lane * 4 + 0];
            float h1 = hs[k][lane * 4 + 1];
            float h2 = hs[k][lane * 4 + 2];
            float h3 = hs[k][lane * 4 + 3];
            aR[0] += wr * h0; aR[1] += wr * h1; aR[2] += wr * h2; aR[3] += wr * h3;
            aZ[0] += wz * h0; aZ[1] += wz * h1; aZ[2] += wz * h2; aZ[3] += wz * h3;
            aN[0] += wn * h0; aN[1] += wn * h1; aN[2] += wn * h2; aN[3] += wn * h3;
        }
        __syncthreads();
    }

    // stage xw (gathered per-batch for bwd dir) + h_old into reused smem
    float* sx = &hs[0][0]; // needs 4096 floats; hs has 8256
    for (int p = tid; p < 384; p += 256) {
        int bi = p / 3, gate = p - bi * 3;
        int len = lengths[bi];
        int seff = d ? ((len - 1 - step) > 0 ? (len - 1 - step) : 0) : step;
        const float* src = &g_xw[(((size_t)d * nS + seff) * nB + bi) * nG + gate * nH + i0];
        float4 v0 = *(const float4*)&src[0];
        float4 v1 = *(const float4*)&src[4];
        float* dst = &sx[gate * 1024 + bi];
        dst[0 * 128] = v0.x; dst[1 * 128] = v0.y; dst[2 * 128] = v0.z; dst[3 * 128] = v0.w;
        dst[4 * 128] = v1.x; dst[5 * 128] = v1.y; dst[6 * 128] = v1.z; dst[7 * 128] = v1.w;
    }
    if (tid < nB) {
        int bi = tid;
        const float* src = &hin[(size_t)bi * nH + i0];
        float4 v0 = *(const float4*)&src[0];
        float4 v1 = *(const float4*)&src[4];
        float* dst = &sx[3072 + bi];
        dst[0 * 128] = v0.x; dst[1 * 128] = v0.y; dst[2 * 128] = v0.z; dst[3 * 128] = v0.w;
        dst[4 * 128] = v1.x; dst[5 * 128] = v1.y; dst[6 * 128] = v1.z; dst[7 * 128] = v1.w;
    }
    __syncthreads();

    int i = i0 + il;
    float br = bh[i], bz = bh[nH + i], bn = bh[2 * nH + i];
#pragma unroll
    for (int j = 0; j < 4; j++) {
        int bi = lane * 4 + j;
        float xr = sx[0 + il * 128 + bi];
        float xz = sx[1024 + il * 128 + bi];
        float xn = sx[2048 + il * 128 + bi];
        float hold = sx[3072 + il * 128 + bi];
        float r = 1.f / (1.f + expf(-(xr + aR[j] + br)));
        float z = 1.f / (1.f + expf(-(xz + aZ[j] + bz)));
        float n = tanhf(xn + r * (aN[j] + bn));
        float hnew = (1.f - z) * n + z * hold;
        int len = lengths[bi];
        bool m = step < len;
        hout[(size_t)bi * nH + i] = m ? hnew : hold;
        g_ys[(((size_t)d * nB + bi) * nS + step) * nH + i] = m ? hnew : 0.f;
    }
}

// ============================================================
// 6) Output: out[b][s][l] = b_lin[l]
//      + sum_{j<512}  ys_f[b][s][j]       * W_lin[l][j]
//      + sum_{j<512} (valid ? ys_b_rev[b][len-1-s][j] : 0) * W_lin[l][512+j]
//    Tile: 32 s x 64 l, K chunks of 64. Grid (4 s-chunks, 128 b).
// ============================================================
__global__ void __launch_bounds__(256) out_kernel(
    const float* __restrict__ Wlin, const float* __restrict__ blin,
    const int* __restrict__ lengths, float* __restrict__ out) {
    int b = blockIdx.y;
    int s0 = blockIdx.x * 32;
    __shared__ float As[64][33];  // [k][s]
    __shared__ float Ws[64][65];  // [k][l]
    int tid = threadIdx.x;
    int l = tid & 63, sg = tid >> 6;
    int len = lengths[b];
    float acc[8] = {0, 0, 0, 0, 0, 0, 0, 0};
    for (int kc = 0; kc < 2 * nH; kc += 64) {
        for (int p = tid; p < 512; p += 256) {
            int ssl = p >> 4, k4 = p & 15;
            int s = s0 + ssl;
            float4 v;
            if (kc < nH) {
                v = *(const float4*)&g_ys[(((size_t)0 * nB + b) * nS + s) * nH + kc + k4 * 4];
            } else if (s < len) {
                int sidx = len - 1 - s;
                v = *(const float4*)&g_ys[(((size_t)1 * nB + b) * nS + sidx) * nH + (kc - nH) + k4 * 4];
            } else {
                v = make_float4(0.f, 0.f, 0.f, 0.f);
            }
            int k = k4 * 4;
            As[k + 0][ssl] = v.x; As[k + 1][ssl] = v.y;
            As[k + 2][ssl] = v.z; As[k + 3][ssl] = v.w;
        }
        for (int p = tid; p < 1024; p += 256) {
            int ll = p >> 4, k4 = p & 15;
            float4 v = *(const float4*)&Wlin[(size_t)ll * (2 * nH) + kc + k4 * 4];
            int k = k4 * 4;
            Ws[k + 0][ll] = v.x; Ws[k + 1][ll] = v.y;
            Ws[k + 2][ll] = v.z; Ws[k + 3][ll] = v.w;
        }
        __syncthreads();
#pragma unroll 4
        for (int k = 0; k < 64; k++) {
            float w = Ws[k][l];
#pragma unroll
            for (int j = 0; j < 8; j++) acc[j] += As[k][sg * 8 + j] * w;
        }
        __syncthreads();
    }
    float bias = blin[l];
#pragma unroll
    for (int j = 0; j < 8; j++) {
        int s = s0 + sg * 8 + j;
        out[((size_t)b * nS + s) * nL + l] = acc[j] + bias;
    }
}

// ============================================================
extern "C" void kernel_launch(void* const* d_in, const int* in_sizes, int n_in,
                              void* d_out, int out_size) {
    const int*   chars   = (const int*)d_in[0];
    const int*   lengths = (const int*)d_in[1];
    const float* forget  = (const float*)d_in[2];
    const float* W_ih_f  = (const float*)d_in[3];
    const float* W_hh_f  = (const float*)d_in[4];
    const float* b_ih_f  = (const float*)d_in[5];
    const float* b_hh_f  = (const float*)d_in[6];
    const float* W_ih_b  = (const float*)d_in[7];
    const float* W_hh_b  = (const float*)d_in[8];
    const float* b_ih_b  = (const float*)d_in[9];
    const float* b_hh_b  = (const float*)d_in[10];
    const float* W_lin   = (const float*)d_in[11];
    const float* b_lin   = (const float*)d_in[12];
    float* out = (float*)d_out;

    // FOFE: one warp per (b,s), 8 warps/block
    fofe_kernel<<<(nB * nS) / 8, 256>>>(chars, forget);
    // transpose input weights
    wt_kernel<<<(2 * nV * nG + 255) / 256, 256>>>(W_ih_f, W_ih_b);
    // input projections, both directions
    dim3 xg(256, 48, 2);
    xw_kernel<<<xg, 256>>>(b_ih_f, b_ih_b);
    // zero h
    hzero_kernel<<<(2 * nB * nH) / 256, 256>>>();
    // sequential scan
    for (int s = 0; s < nS; s++) {
        scan_kernel<<<128, 256>>>(s, s & 1, W_hh_f, b_hh_f, W_hh_b, b_hh_b, lengths);
    }
    // output head
    dim3 og(4, nB);
    out_kernel<<<og, 256>>>(W_lin, b_lin, lengths, out);
}

// round 4
// speedup vs baseline: 1.7303x; 1.7303x over previous
#include <cuda_runtime.h>
#include <math.h>

typedef unsigned long long ull;

// Problem dims
constexpr int nB = 128;
constexpr int nS = 128;
constexpr int nW = 16;
constexpr int nV = 128;
constexpr int nH = 512;
constexpr int nL = 64;
constexpr int nG = 3 * nH;     // 1536
constexpr int NBLK = 128;      // persistent scan blocks (<= 148 SMs)

// ---- scratch (device globals; no allocations allowed) ----
__device__ float g_WT[2][nV * nG];            // W_ih transposed [d][v][g]
__device__ float g_xw[2ull * nS * nB * nG];   // [d][s][b][g]
__device__ float g_ys[2ull * nS * nH * nB];   // [d][s][i][b]
__device__ float g_h[2][2][nH * nB];          // [parity][d][i][b]
__device__ unsigned g_count = 0;              // grid barrier arrivals
__device__ unsigned g_gen = 0;                // grid barrier generation

// ============================================================
// helpers
// ============================================================
__device__ __forceinline__ void fma2(ull& d, ull a, ull b) {
    // packed 2x fp32 fma (Blackwell f32x2)
    asm("fma.rn.f32x2 %0, %1, %2, %0;" : "+l"(d) : "l"(a), "l"(b));
}
__device__ __forceinline__ void cpa16(unsigned dst, const void* src) {
    asm volatile("cp.async.cg.shared.global [%0], [%1], 16;" :: "r"(dst), "l"(src));
}
__device__ __forceinline__ void cpa_commit() {
    asm volatile("cp.async.commit_group;");
}
template <int N>
__device__ __forceinline__ void cpa_wait() {
    asm volatile("cp.async.wait_group %0;" :: "n"(N));
}
__device__ __forceinline__ float sigf(float x) {
    return 1.f / (1.f + expf(-x));
}

// sense-counting grid barrier across NBLK co-resident blocks
__device__ __forceinline__ void grid_barrier(unsigned target) {
    __threadfence();          // make this thread's stores visible (L2)
    __syncthreads();          // all block stores ordered before thread0 arrival
    if (threadIdx.x == 0) {
        unsigned t = atomicAdd(&g_count, 1);
        if (t == NBLK - 1) {
            g_count = 0;
            __threadfence();
            atomicExch(&g_gen, target);
        } else {
            unsigned v;
            do {
                asm volatile("ld.volatile.global.u32 %0, [%1];" : "=r"(v) : "l"(&g_gen));
            } while (v != target);
            __threadfence();
        }
    }
    __syncthreads();
}

// ============================================================
// 1) Transpose W_ih (g,v) -> (v,g)
// ============================================================
__global__ void wt_kernel(const float* __restrict__ Wf,
                          const float* __restrict__ Wb) {
    int idx = blockIdx.x * 256 + threadIdx.x;
    if (idx >= 2 * nV * nG) return;
    int d = idx / (nV * nG);
    int rem = idx - d * (nV * nG);
    int v = rem / nG, g = rem - v * nG;
    const float* Wsrc = d ? Wb : Wf;
    g_WT[d][rem] = Wsrc[g * nV + v];
}

// ============================================================
// 2) Sparse input projection straight from chars (<=16 nnz per row):
//    xw[d][s][b][g] = b_ih[g] + sum_w wt(b,s,w) * W_ih[g][chars(b,s,w)]
//    Block = (g-chunk of 128, s, d). W chunk cached in smem.
// ============================================================
__global__ void __launch_bounds__(256) xwk(const int* __restrict__ chars,
                                           const float* __restrict__ forget,
                                           const float* __restrict__ bihf,
                                           const float* __restrict__ bihb) {
    extern __shared__ float sm[];
    float* Wv  = sm;                       // [128 v][128 g]
    float* swt = sm + 16384;               // [128 b][16]
    int*   sc  = (int*)(sm + 18432);       // [128 b][16]
    float* fp  = sm + 20480;               // forget powers [17]

    int gc = blockIdx.x, s = blockIdx.y, d = blockIdx.z;
    int tid = threadIdx.x;

    const float* WT = g_WT[d];
    for (int p = tid; p < 4096; p += 256) {
        int v = p >> 5, g4 = p & 31;
        *(float4*)&Wv[v * 128 + g4 * 4] =
            *(const float4*)&WT[(size_t)v * nG + gc * 128 + g4 * 4];
    }
    if (tid == 0) {
        float f = *forget;
        fp[0] = 1.f;
        for (int i = 1; i <= 16; i++) fp[i] = fp[i - 1] * f;
    }
    __syncthreads();
    if (tid < 128) {
        int b = tid;
        const int* cp = chars + ((size_t)b * nS + s) * nW;
        int c[16];
#pragma unroll
        for (int w = 0; w < 16; w++) c[w] = cp[w];
        int cnt = 0;
#pragma unroll
        for (int w = 15; w >= 0; w--) {
            bool nz = (c[w] != 0);
            swt[b * 16 + w] = nz ? fp[cnt] : 0.f;
            sc[b * 16 + w] = c[w];
            cnt += nz ? 1 : 0;
        }
    }
    __syncthreads();

    int gq = tid & 31, rp = tid >> 5;
    const float* bih = d ? bihb : bihf;
    float4 bias = *(const float4*)&bih[gc * 128 + gq * 4];
    for (int it = 0; it < 16; it++) {
        int b = it * 8 + rp;
        float a0 = bias.x, a1 = bias.y, a2 = bias.z, a3 = bias.w;
#pragma unroll
        for (int w = 0; w < 16; w++) {
            float ww = swt[b * 16 + w];
            int cc = sc[b * 16 + w];
            float4 wv = *(const float4*)&Wv[cc * 128 + gq * 4];
            a0 += ww * wv.x; a1 += ww * wv.y; a2 += ww * wv.z; a3 += ww * wv.w;
        }
        *(float4*)&g_xw[(((size_t)d * nS + s) * nB + b) * nG + gc * 128 + gq * 4] =
            make_float4(a0, a1, a2, a3);
    }
}

// ============================================================
// 3) Persistent bidirectional GRU scan.
//    128 blocks: d = blk>>6, i-chunk of 8 hidden units = blk&63.
//    Warp w: i-pair (i0 + (w&3)*2, +1), batch half (w>>2)*64, 2 batches/lane.
//    W_hh resident in smem as duplicated f32x2 pairs; h double-buffered via
//    cp.async.cg; FFMA2 inner loop; custom grid barrier per step.
// ============================================================
__global__ void __launch_bounds__(256, 1) scan_kernel(
    const float* __restrict__ Whf, const float* __restrict__ bhf,
    const float* __restrict__ Whb, const float* __restrict__ bhb,
    const int* __restrict__ lengths) {
    extern __shared__ float sm[];
    ull*   Wd    = (ull*)sm;            // [24 rows][512 k] dup pairs (96 KB)
    float* hsf   = sm + 24576;          // [2][64 k][128 b] (64 KB)
    float* sxw   = sm + 40960;          // [3 gate][8 r][128 b]
    float* shold = sm + 44032;          // [8 r][128 b]
    int*   lensm = (int*)(sm + 45056);  // [128]
    unsigned* sbase = (unsigned*)(sm + 45184);

    int tid = threadIdx.x;
    int d = blockIdx.x >> 6, ic = blockIdx.x & 63, i0 = ic * 8;
    const float* Wh = d ? Whb : Whf;
    const float* bh = d ? bhb : bhf;

    // load 24 W rows (3 gates x 8 i) once, duplicated into f32x2 pairs
    for (int p = tid; p < 3072; p += 256) {
        int row = p >> 7, k4 = p & 127;
        float4 v = *(const float4*)&Wh[((size_t)(row >> 3) * nH + i0 + (row & 7)) * nH + k4 * 4];
        float2* dst = (float2*)&Wd[(size_t)row * 512 + k4 * 4];
        dst[0] = make_float2(v.x, v.x); dst[1] = make_float2(v.y, v.y);
        dst[2] = make_float2(v.z, v.z); dst[3] = make_float2(v.w, v.w);
    }
    if (tid < 128) lensm[tid] = lengths[tid];
    if (tid == 0) {
        unsigned v;
        asm volatile("ld.volatile.global.u32 %0, [%1];" : "=r"(v) : "l"(&g_gen));
        *sbase = v;
    }
    // zero initial hidden state (parity 0), this block's rows
    for (int p = tid; p < 1024; p += 256)
        g_h[0][d][(size_t)(i0 + (p >> 7)) * nB + (p & 127)] = 0.f;
    __syncthreads();
    unsigned base = *sbase;
    grid_barrier(base + 1);

    int w = tid >> 5, lane = tid & 31;
    int r0 = (w & 3) * 2;
    int b0 = ((w & 4) << 4) + lane * 2;   // (w>>2)*64 + lane*2
    const ull* W00 = Wd + (size_t)(0 * 8 + r0) * 512;
    const ull* W01 = W00 + 512;
    const ull* W10 = Wd + (size_t)(1 * 8 + r0) * 512;
    const ull* W11 = W10 + 512;
    const ull* W20 = Wd + (size_t)(2 * 8 + r0) * 512;
    const ull* W21 = W20 + 512;
    int i_a = i0 + r0, i_b = i0 + r0 + 1;
    float bRa = bh[i_a], bRb = bh[i_b];
    float bZa = bh[nH + i_a], bZb = bh[nH + i_b];
    float bNa = bh[2 * nH + i_a], bNb = bh[2 * nH + i_b];
    unsigned hs_smem = (unsigned)__cvta_generic_to_shared(hsf);
    int len0 = lensm[b0], len1 = lensm[b0 + 1];

    for (int step = 0; step < nS; step++) {
        int par = step & 1;
        const float* hin = g_h[par][d];
        float* hout = g_h[par ^ 1][d];

        // stage chunk 0
#pragma unroll
        for (int q = 0; q < 8; q++) {
            int p = tid + q * 256;
            int kk = p >> 5, b4 = (p & 31) * 4;
            cpa16(hs_smem + (unsigned)((kk * 128 + b4) * 4), hin + (size_t)kk * nB + b4);
        }
        cpa_commit();

        ull a00 = 0, a01 = 0, a10 = 0, a11 = 0, a20 = 0, a21 = 0;
        for (int c = 0; c < 8; c++) {
            if (c < 7) {
                int kc2 = (c + 1) * 64;
                int buf2 = (c + 1) & 1;
#pragma unroll
                for (int q = 0; q < 8; q++) {
                    int p = tid + q * 256;
                    int kk = p >> 5, b4 = (p & 31) * 4;
                    cpa16(hs_smem + (unsigned)((buf2 * 8192 + kk * 128 + b4) * 4),
                          hin + (size_t)(kc2 + kk) * nB + b4);
                }
                cpa_commit();
                cpa_wait<1>();
            } else {
                cpa_wait<0>();
            }
            __syncthreads();
            const float* hc = hsf + (c & 1) * 8192 + b0;
            const ull* p00 = W00 + c * 64; const ull* p01 = W01 + c * 64;
            const ull* p10 = W10 + c * 64; const ull* p11 = W11 + c * 64;
            const ull* p20 = W20 + c * 64; const ull* p21 = W21 + c * 64;
#pragma unroll
            for (int k = 0; k < 64; k++) {
                ull h = *(const ull*)(hc + k * 128);
                fma2(a00, p00[k], h); fma2(a01, p01[k], h);
                fma2(a10, p10[k], h); fma2(a11, p11[k], h);
                fma2(a20, p20[k], h); fma2(a21, p21[k], h);
            }
            __syncthreads();
        }

        // stage xw gates (gathered seq index for backward dir) + h_old
        for (int p = tid; p < 384; p += 256) {
            int gate = p >> 7, b = p & 127;
            int len = lensm[b];
            int seff = d ? ((len - 1 - step) > 0 ? (len - 1 - step) : 0) : step;
            const float4* src = (const float4*)
                &g_xw[(((size_t)d * nS + seff) * nB + b) * nG + gate * nH + i0];
            float4 v0 = src[0], v1 = src[1];
            float* dst = sxw + gate * 1024 + b;
            dst[0] = v0.x; dst[128] = v0.y; dst[256] = v0.z; dst[384] = v0.w;
            dst[512] = v1.x; dst[640] = v1.y; dst[768] = v1.z; dst[896] = v1.w;
        }
        if (tid < 128) {
            int b = tid;
#pragma unroll
            for (int r = 0; r < 8; r++)
                shold[r * 128 + b] = __ldcg(&hin[(size_t)(i0 + r) * nB + b]);
        }
        __syncthreads();

        float2 aR[2] = { *(float2*)&a00, *(float2*)&a01 };
        float2 aZ[2] = { *(float2*)&a10, *(float2*)&a11 };
        float2 aN[2] = { *(float2*)&a20, *(float2*)&a21 };
        float bR[2] = { bRa, bRb }, bZ[2] = { bZa, bZb }, bN[2] = { bNa, bNb };
        int iv[2] = { i_a, i_b };
        bool m0 = step < len0, m1 = step < len1;
#pragma unroll
        for (int ii = 0; ii < 2; ii++) {
            int rr = r0 + ii;
            float2 xr = *(float2*)&sxw[0 + rr * 128 + b0];
            float2 xz = *(float2*)&sxw[1024 + rr * 128 + b0];
            float2 xn = *(float2*)&sxw[2048 + rr * 128 + b0];
            float2 hold = *(float2*)&shold[rr * 128 + b0];
            float rg0 = sigf(xr.x + aR[ii].x + bR[ii]);
            float rg1 = sigf(xr.y + aR[ii].y + bR[ii]);
            float zg0 = sigf(xz.x + aZ[ii].x + bZ[ii]);
            float zg1 = sigf(xz.y + aZ[ii].y + bZ[ii]);
            float ng0 = tanhf(xn.x + rg0 * (aN[ii].x + bN[ii]));
            float ng1 = tanhf(xn.y + rg1 * (aN[ii].y + bN[ii]));
            float hn0 = (1.f - zg0) * ng0 + zg0 * hold.x;
            float hn1 = (1.f - zg1) * ng1 + zg1 * hold.y;
            float2 ho = make_float2(m0 ? hn0 : hold.x, m1 ? hn1 : hold.y);
            float2 yv = make_float2(m0 ? hn0 : 0.f, m1 ? hn1 : 0.f);
            *(float2*)&hout[(size_t)iv[ii] * nB + b0] = ho;
            *(float2*)&g_ys[(((size_t)d * nS + step) * nH + iv[ii]) * nB + b0] = yv;
        }
        grid_barrier(base + 2 + step);
    }
}

// ============================================================
// 4) Output head: out[b][s][l] = b_lin[l]
//      + sum_k ys_f[s][k][b] * Wl[l][k]
//      + (s<len) sum_k ys_b[len-1-s][k][b] * Wl[l][512+k]
//    Block = (b-half of 64, s). Tile 64b x 64l, K = 1024 in chunks of 64.
//    NOTE: final staging goes through As (stride 64, 16B-aligned rows);
//    Ws stays padded (65) for the K-loop broadcast reads only.
// ============================================================
__global__ void __launch_bounds__(256) out_kernel(
    const float* __restrict__ Wlin, const float* __restrict__ blin,
    const int* __restrict__ lengths, float* __restrict__ out) {
    __shared__ float As[64][64];
    __shared__ float Ws[64][65];
    __shared__ int lensm[64];
    int bh = blockIdx.x, s = blockIdx.y;
    int tid = threadIdx.x;
    if (tid < 64) lensm[tid] = lengths[bh * 64 + tid];
    int l = tid & 63, bg = tid >> 6;
    float acc[16];
#pragma unroll
    for (int j = 0; j < 16; j++) acc[j] = 0.f;

    for (int kc = 0; kc < 1024; kc += 64) {
        __syncthreads();
        if (kc < 512) {
            for (int p = tid; p < 1024; p += 256) {
                int kk = p >> 4, b4 = (p & 15) * 4;
                *(float4*)&As[kk][b4] = *(const float4*)
                    &g_ys[(((size_t)0 * nS + s) * nH + kc + kk) * nB + bh * 64 + b4];
            }
        } else {
            for (int p = tid; p < 4096; p += 256) {
                int kk = p >> 6, bb = p & 63;
                int b = bh * 64 + bb, len = lensm[bb];
                float v = 0.f;
                if (s < len) {
                    int t = len - 1 - s;
                    v = g_ys[(((size_t)1 * nS + t) * nH + (kc - 512 + kk)) * nB + b];
                }
                As[kk][bb] = v;
            }
        }
        for (int p = tid; p < 1024; p += 256) {
            int ll = p >> 4, k = (p & 15) * 4;
            float4 v = *(const float4*)&Wlin[(size_t)ll * 1024 + kc + k];
            Ws[k + 0][ll] = v.x; Ws[k + 1][ll] = v.y;
            Ws[k + 2][ll] = v.z; Ws[k + 3][ll] = v.w;
        }
        __syncthreads();
#pragma unroll 8
        for (int kk = 0; kk < 64; kk++) {
            float wv = Ws[kk][l];
            float4 h0 = *(float4*)&As[kk][bg * 16 + 0];
            float4 h1 = *(float4*)&As[kk][bg * 16 + 4];
            float4 h2 = *(float4*)&As[kk][bg * 16 + 8];
            float4 h3 = *(float4*)&As[kk][bg * 16 + 12];
            acc[0] += h0.x * wv; acc[1] += h0.y * wv; acc[2] += h0.z * wv; acc[3] += h0.w * wv;
            acc[4] += h1.x * wv; acc[5] += h1.y * wv; acc[6] += h1.z * wv; acc[7] += h1.w * wv;
            acc[8] += h2.x * wv; acc[9] += h2.y * wv; acc[10] += h2.z * wv; acc[11] += h2.w * wv;
            acc[12] += h3.x * wv; acc[13] += h3.y * wv; acc[14] += h3.z * wv; acc[15] += h3.w * wv;
        }
    }
    __syncthreads();
    float bias = blin[l];
    // stage result: out tile [b][l] into As (stride 64 -> aligned float4 rows)
#pragma unroll
    for (int j = 0; j < 16; j++) As[bg * 16 + j][l] = acc[j] + bias;
    __syncthreads();
    for (int p = tid; p < 1024; p += 256) {
        int bb = p >> 4, l4 = (p & 15) * 4;
        *(float4*)&out[(size_t)(bh * 64 + bb) * nS * nL + s * nL + l4] =
            *(float4*)&As[bb][l4];
    }
}

// ============================================================
extern "C" void kernel_launch(void* const* d_in, const int* in_sizes, int n_in,
                              void* d_out, int out_size) {
    const int*   chars   = (const int*)d_in[0];
    const int*   lengths = (const int*)d_in[1];
    const float* forget  = (const float*)d_in[2];
    const float* W_ih_f  = (const float*)d_in[3];
    const float* W_hh_f  = (const float*)d_in[4];
    const float* b_ih_f  = (const float*)d_in[5];
    const float* b_hh_f  = (const float*)d_in[6];
    const float* W_ih_b  = (const float*)d_in[7];
    const float* W_hh_b  = (const float*)d_in[8];
    const float* b_ih_b  = (const float*)d_in[9];
    const float* b_hh_b  = (const float*)d_in[10];
    const float* W_lin   = (const float*)d_in[11];
    const float* b_lin   = (const float*)d_in[12];
    float* out = (float*)d_out;

    cudaFuncSetAttribute(xwk, cudaFuncAttributeMaxDynamicSharedMemorySize, 90 * 1024);
    cudaFuncSetAttribute(scan_kernel, cudaFuncAttributeMaxDynamicSharedMemorySize, 185 * 1024);

    wt_kernel<<<(2 * nV * nG + 255) / 256, 256>>>(W_ih_f, W_ih_b);
    xwk<<<dim3(12, 128, 2), 256, 82000>>>(chars, forget, b_ih_f, b_ih_b);
    scan_kernel<<<NBLK, 256, 181000>>>(W_hh_f, b_hh_f, W_hh_b, b_hh_b, lengths);
    out_kernel<<<dim3(2, 128), 256>>>(W_lin, b_lin, lengths, out);
}

// round 5
// speedup vs baseline: 2.3228x; 1.3424x over previous
#include <cuda_runtime.h>
#include <math.h>

typedef unsigned long long ull;

// Problem dims
constexpr int nB = 128;
constexpr int nS = 128;
constexpr int nV = 128;
constexpr int nH = 512;
constexpr int nL = 64;
constexpr int nG = 3 * nH;     // 1536
constexpr int NBLK = 128;      // persistent scan blocks (<= 148 SMs)

// ---- scratch (device globals; no allocations allowed) ----
__device__ float g_WT[2][nV * nG];            // W_ih transposed [d][v][g]
__device__ float g_xw[2ull * nS * nB * nG];   // [d][s][b][g]
__device__ float g_ys[2ull * nS * nH * nB];   // [d][s][i][b]
// h interleaved: [parity][d][k2][b][2]  (element j of pair k2 = h[2*k2+j][b])
__device__ float g_h[2][2][nH * nB];
__device__ unsigned g_count = 0;              // grid barrier arrivals
__device__ unsigned g_gen = 0;                // grid barrier generation

// ============================================================
// helpers
// ============================================================
__device__ __forceinline__ void fma2(ull& d, ull a, ull b) {
    asm("fma.rn.f32x2 %0, %1, %2, %0;" : "+l"(d) : "l"(a), "l"(b));
}
__device__ __forceinline__ void cpa16(unsigned dst, const void* src) {
    asm volatile("cp.async.cg.shared.global [%0], [%1], 16;" :: "r"(dst), "l"(src));
}
__device__ __forceinline__ void cpa_commit() {
    asm volatile("cp.async.commit_group;");
}
template <int N>
__device__ __forceinline__ void cpa_wait() {
    asm volatile("cp.async.wait_group %0;" :: "n"(N));
}
__device__ __forceinline__ float sigf(float x) {
    return 1.f / (1.f + expf(-x));
}

// sense-counting grid barrier across NBLK co-resident blocks
__device__ __forceinline__ void grid_barrier(unsigned target) {
    __threadfence();
    __syncthreads();
    if (threadIdx.x == 0) {
        unsigned t = atomicAdd(&g_count, 1);
        if (t == NBLK - 1) {
            g_count = 0;
            __threadfence();
            atomicExch(&g_gen, target);
        } else {
            unsigned v;
            do {
                asm volatile("ld.volatile.global.u32 %0, [%1];" : "=r"(v) : "l"(&g_gen));
            } while (v != target);
            __threadfence();
        }
    }
    __syncthreads();
}

// ============================================================
// 1) Transpose W_ih (g,v) -> (v,g)
// ============================================================
__global__ void wt_kernel(const float* __restrict__ Wf,
                          const float* __restrict__ Wb) {
    int idx = blockIdx.x * 256 + threadIdx.x;
    if (idx >= 2 * nV * nG) return;
    int d = idx / (nV * nG);
    int rem = idx - d * (nV * nG);
    int v = rem / nG, g = rem - v * nG;
    const float* Wsrc = d ? Wb : Wf;
    g_WT[d][rem] = Wsrc[g * nV + v];
}

// ============================================================
// 2) Sparse input projection straight from chars (<=16 nnz per row)
// ============================================================
__global__ void __launch_bounds__(256) xwk(const int* __restrict__ chars,
                                           const float* __restrict__ forget,
                                           const float* __restrict__ bihf,
                                           const float* __restrict__ bihb) {
    extern __shared__ float sm[];
    float* Wv  = sm;                       // [128 v][128 g]
    float* swt = sm + 16384;               // [128 b][16]
    int*   sc  = (int*)(sm + 18432);       // [128 b][16]
    float* fp  = sm + 20480;               // forget powers [17]

    int gc = blockIdx.x, s = blockIdx.y, d = blockIdx.z;
    int tid = threadIdx.x;

    const float* WT = g_WT[d];
    for (int p = tid; p < 4096; p += 256) {
        int v = p >> 5, g4 = p & 31;
        *(float4*)&Wv[v * 128 + g4 * 4] =
            *(const float4*)&WT[(size_t)v * nG + gc * 128 + g4 * 4];
    }
    if (tid == 0) {
        float f = *forget;
        fp[0] = 1.f;
        for (int i = 1; i <= 16; i++) fp[i] = fp[i - 1] * f;
    }
    __syncthreads();
    if (tid < 128) {
        int b = tid;
        const int* cp = chars + ((size_t)b * nS + s) * 16;
        int c[16];
#pragma unroll
        for (int w = 0; w < 16; w++) c[w] = cp[w];
        int cnt = 0;
#pragma unroll
        for (int w = 15; w >= 0; w--) {
            bool nz = (c[w] != 0);
            swt[b * 16 + w] = nz ? fp[cnt] : 0.f;
            sc[b * 16 + w] = c[w];
            cnt += nz ? 1 : 0;
        }
    }
    __syncthreads();

    int gq = tid & 31, rp = tid >> 5;
    const float* bih = d ? bihb : bihf;
    float4 bias = *(const float4*)&bih[gc * 128 + gq * 4];
    for (int it = 0; it < 16; it++) {
        int b = it * 8 + rp;
        float a0 = bias.x, a1 = bias.y, a2 = bias.z, a3 = bias.w;
#pragma unroll
        for (int w = 0; w < 16; w++) {
            float ww = swt[b * 16 + w];
            int cc = sc[b * 16 + w];
            float4 wv = *(const float4*)&Wv[cc * 128 + gq * 4];
            a0 += ww * wv.x; a1 += ww * wv.y; a2 += ww * wv.z; a3 += ww * wv.w;
        }
        *(float4*)&g_xw[(((size_t)d * nS + s) * nB + b) * nG + gc * 128 + gq * 4] =
            make_float4(a0, a1, a2, a3);
    }
}

// ============================================================
// 3) Persistent bidirectional GRU scan (FFMA2-bound inner loop).
//    128 blocks: d = blk>>6, i-chunk of 8 = blk&63.
//    Warp w: rows r0=2*(w&3), r0+1 (x3 gates); batch half (w>>2), 2 b/lane.
//    Accumulators are (even-k, odd-k) f32x2 partials; W rows in natural
//    float2 form read via LDS.128 (4 k / load); h interleaved [k2][b][2]
//    so one LDS.128 feeds 2 k x 2 b. 8 LDS.128 + 24 FFMA2 per 4-k iter.
// ============================================================
__global__ void __launch_bounds__(256, 1) scan_kernel(
    const float* __restrict__ Whf, const float* __restrict__ bhf,
    const float* __restrict__ Whb, const float* __restrict__ bhb,
    const int* __restrict__ lengths) {
    extern __shared__ float sm[];
    float* Wsm  = sm;                    // [24 rows][512 k] natural order (48 KB)
    float* hsf  = sm + 12288;            // 2 x [32 k2][128 b][2] (64 KB)
    float* sxw  = sm + 28672;            // [3 gate][128 b][8 r] (12 KB)
    float* sxh  = sm + 31744;            // [4 k2][128 b][2] h_old (4 KB)
    int*   lensm = (int*)(sm + 32768);   // [128]
    unsigned* sbase = (unsigned*)(sm + 32896);

    int tid = threadIdx.x;
    int d = blockIdx.x >> 6, ic = blockIdx.x & 63, i0 = ic * 8;
    const float* Wh = d ? Whb : Whf;
    const float* bh = d ? bhb : bhf;

    // load 24 W rows (3 gates x 8 i) once, natural layout
    for (int p = tid; p < 3072; p += 256) {
        int row = p >> 7, q = p & 127;
        float4 v = *(const float4*)&Wh[((size_t)(row >> 3) * nH + i0 + (row & 7)) * nH + q * 4];
        *(float4*)&Wsm[row * 512 + q * 4] = v;
    }
    if (tid < 128) lensm[tid] = lengths[tid];
    if (tid == 0) {
        unsigned v;
        asm volatile("ld.volatile.global.u32 %0, [%1];" : "=r"(v) : "l"(&g_gen));
        *sbase = v;
    }
    // zero initial hidden state (parity 0), this block's k2 slice
    for (int p = tid; p < 1024; p += 256)
        g_h[0][d][(size_t)(i0 >> 1) * 256 + p] = 0.f;
    __syncthreads();
    unsigned base = *sbase;
    grid_barrier(base + 1);

    int w = tid >> 5, lane = tid & 31;
    int r0 = (w & 3) * 2;
    int b0 = ((w & 4) << 4) + lane * 2;   // (w>>2)*64 + lane*2
    int i_a = i0 + r0, i_b = i_a + 1;
    float bRa = bh[i_a], bRb = bh[i_b];
    float bZa = bh[nH + i_a], bZb = bh[nH + i_b];
    float bNa = bh[2 * nH + i_a], bNb = bh[2 * nH + i_b];
    unsigned hsf_s = (unsigned)__cvta_generic_to_shared(hsf);
    unsigned sxw_s = (unsigned)__cvta_generic_to_shared(sxw);
    unsigned sxh_s = (unsigned)__cvta_generic_to_shared(sxh);
    int len0 = lensm[b0], len1 = lensm[b0 + 1];

    // per-warp weight row base pointers [gate][ii]
    const float* wp[3][2];
#pragma unroll
    for (int g = 0; g < 3; g++)
#pragma unroll
        for (int ii = 0; ii < 2; ii++)
            wp[g][ii] = Wsm + ((g * 8 + r0 + ii) << 9);

    for (int step = 0; step < nS; step++) {
        int par = step & 1;
        const float* hin = g_h[par][d];
        float* hout = g_h[par ^ 1][d];

        // --- prefetch group X: xw gather (bwd dir reversed index) + h_old ---
#pragma unroll
        for (int q = 0; q < 3; q++) {
            int p = tid + q * 256;               // < 768
            int gate = p >> 8, rem = p & 255;
            int b = rem >> 1, half = rem & 1;
            int len = lensm[b];
            int seff = d ? ((len - 1 - step) > 0 ? (len - 1 - step) : 0) : step;
            const float* src = &g_xw[(((size_t)d * nS + seff) * nB + b) * nG
                                     + gate * nH + i0 + half * 4];
            cpa16(sxw_s + (unsigned)((gate * 1024 + b * 8 + half * 4) * 4), src);
        }
        {
            int k2l = tid >> 6, bq = tid & 63;
            const float* src = hin + ((size_t)(i0 >> 1) + k2l) * 256 + bq * 4;
            cpa16(sxh_s + (unsigned)((k2l * 256 + bq * 4) * 4), src);
        }
        cpa_commit();
        // --- prefetch chunk 0 ---
#pragma unroll
        for (int q = 0; q < 8; q++) {
            int p = tid + q * 256;
            cpa16(hsf_s + (unsigned)(p * 16), hin + p * 4);
        }
        cpa_commit();

        ull acc[3][2][2];
#pragma unroll
        for (int g = 0; g < 3; g++)
#pragma unroll
            for (int ii = 0; ii < 2; ii++)
#pragma unroll
                for (int bs = 0; bs < 2; bs++) acc[g][ii][bs] = 0ull;

        for (int c = 0; c < 8; c++) {
            cpa_wait<0>();
            __syncthreads();
            if (c < 7) {
                const float* srcb = hin + (size_t)(c + 1) * 8192;
                unsigned dstb = hsf_s + (unsigned)((((c + 1) & 1) * 8192) * 4);
#pragma unroll
                for (int q = 0; q < 8; q++) {
                    int p = tid + q * 256;
                    cpa16(dstb + (unsigned)(p * 16), srcb + p * 4);
                }
                cpa_commit();
            }
            const float* hcc = hsf + (c & 1) * 8192 + (b0 << 1);
            int co = c << 6;   // chunk offset in floats within W row
#pragma unroll
            for (int t = 0; t < 16; t++) {
                // h: pairs for k2 = 2t (hA) and 2t+1 (hB), batches b0,b0+1
                ulonglong2 hA = *(const ulonglong2*)(hcc + (t << 9));
                ulonglong2 hB = *(const ulonglong2*)(hcc + (t << 9) + 256);
#pragma unroll
                for (int g = 0; g < 3; g++) {
#pragma unroll
                    for (int ii = 0; ii < 2; ii++) {
                        ulonglong2 wv = *(const ulonglong2*)(wp[g][ii] + co + (t << 2));
                        fma2(acc[g][ii][0], wv.x, hA.x);
                        fma2(acc[g][ii][0], wv.y, hB.x);
                        fma2(acc[g][ii][1], wv.x, hA.y);
                        fma2(acc[g][ii][1], wv.y, hB.y);
                    }
                }
            }
            __syncthreads();
        }

        // fold (even,odd) partials
        float sR[2][2], sZ[2][2], sN[2][2];
#pragma unroll
        for (int ii = 0; ii < 2; ii++)
#pragma unroll
            for (int bs = 0; bs < 2; bs++) {
                float2 r = *(float2*)&acc[0][ii][bs]; sR[ii][bs] = r.x + r.y;
                float2 z = *(float2*)&acc[1][ii][bs]; sZ[ii][bs] = z.x + z.y;
                float2 n = *(float2*)&acc[2][ii][bs]; sN[ii][bs] = n.x + n.y;
            }

        float bR[2] = { bRa, bRb }, bZ[2] = { bZa, bZb }, bN[2] = { bNa, bNb };
        const float* sxhb = sxh + (r0 >> 1) * 256;
        float ho[2][2], yv[2][2];
        bool msk[2] = { step < len0, step < len1 };
#pragma unroll
        for (int ii = 0; ii < 2; ii++) {
            int rr = r0 + ii;
#pragma unroll
            for (int bs = 0; bs < 2; bs++) {
                int b = b0 + bs;
                float xr = sxw[b * 8 + rr];
                float xz = sxw[1024 + b * 8 + rr];
                float xn = sxw[2048 + b * 8 + rr];
                float hold = sxhb[b * 2 + ii];
                float rg = sigf(xr + sR[ii][bs] + bR[ii]);
                float zg = sigf(xz + sZ[ii][bs] + bZ[ii]);
                float ng = tanhf(xn + rg * (sN[ii][bs] + bN[ii]));
                float hn = (1.f - zg) * ng + zg * hold;
                ho[ii][bs] = msk[bs] ? hn : hold;
                yv[ii][bs] = msk[bs] ? hn : 0.f;
            }
        }
        // h write: one STG.128 (interleaved layout), ys: 2x STG.64
        *(float4*)&hout[(size_t)(i_a >> 1) * 256 + b0 * 2] =
            make_float4(ho[0][0], ho[1][0], ho[0][1], ho[1][1]);
#pragma unroll
        for (int ii = 0; ii < 2; ii++)
            *(float2*)&g_ys[(((size_t)d * nS + step) * nH + i0 + r0 + ii) * nB + b0] =
                make_float2(yv[ii][0], yv[ii][1]);

        grid_barrier(base + 2 + step);
    }
}

// ============================================================
// 4) Output head (unchanged from R4)
// ============================================================
__global__ void __launch_bounds__(256) out_kernel(
    const float* __restrict__ Wlin, const float* __restrict__ blin,
    const int* __restrict__ lengths, float* __restrict__ out) {
    __shared__ float As[64][64];
    __shared__ float Ws[64][65];
    __shared__ int lensm[64];
    int bh = blockIdx.x, s = blockIdx.y;
    int tid = threadIdx.x;
    if (tid < 64) lensm[tid] = lengths[bh * 64 + tid];
    int l = tid & 63, bg = tid >> 6;
    float acc[16];
#pragma unroll
    for (int j = 0; j < 16; j++) acc[j] = 0.f;

    for (int kc = 0; kc < 1024; kc += 64) {
        __syncthreads();
        if (kc < 512) {
            for (int p = tid; p < 1024; p += 256) {
                int kk = p >> 4, b4 = (p & 15) * 4;
                *(float4*)&As[kk][b4] = *(const float4*)
                    &g_ys[(((size_t)0 * nS + s) * nH + kc + kk) * nB + bh * 64 + b4];
            }
        } else {
            for (int p = tid; p < 4096; p += 256) {
                int kk = p >> 6, bb = p & 63;
                int b = bh * 64 + bb, len = lensm[bb];
                float v = 0.f;
                if (s < len) {
                    int t = len - 1 - s;
                    v = g_ys[(((size_t)1 * nS + t) * nH + (kc - 512 + kk)) * nB + b];
                }
                As[kk][bb] = v;
            }
        }
        for (int p = tid; p < 1024; p += 256) {
            int ll = p >> 4, k = (p & 15) * 4;
            float4 v = *(const float4*)&Wlin[(size_t)ll * 1024 + kc + k];
            Ws[k + 0][ll] = v.x; Ws[k + 1][ll] = v.y;
            Ws[k + 2][ll] = v.z; Ws[k + 3][ll] = v.w;
        }
        __syncthreads();
#pragma unroll 8
        for (int kk = 0; kk < 64; kk++) {
            float wv = Ws[kk][l];
            float4 h0 = *(float4*)&As[kk][bg * 16 + 0];
            float4 h1 = *(float4*)&As[kk][bg * 16 + 4];
            float4 h2 = *(float4*)&As[kk][bg * 16 + 8];
            float4 h3 = *(float4*)&As[kk][bg * 16 + 12];
            acc[0] += h0.x * wv; acc[1] += h0.y * wv; acc[2] += h0.z * wv; acc[3] += h0.w * wv;
            acc[4] += h1.x * wv; acc[5] += h1.y * wv; acc[6] += h1.z * wv; acc[7] += h1.w * wv;
            acc[8] += h2.x * wv; acc[9] += h2.y * wv; acc[10] += h2.z * wv; acc[11] += h2.w * wv;
            acc[12] += h3.x * wv; acc[13] += h3.y * wv; acc[14] += h3.z * wv; acc[15] += h3.w * wv;
        }
    }
    __syncthreads();
    float bias = blin[l];
#pragma unroll
    for (int j = 0; j < 16; j++) As[bg * 16 + j][l] = acc[j] + bias;
    __syncthreads();
    for (int p = tid; p < 1024; p += 256) {
        int bb = p >> 4, l4 = (p & 15) * 4;
        *(float4*)&out[(size_t)(bh * 64 + bb) * nS * nL + s * nL + l4] =
            *(float4*)&As[bb][l4];
    }
}

// ============================================================
extern "C" void kernel_launch(void* const* d_in, const int* in_sizes, int n_in,
                              void* d_out, int out_size) {
    const int*   chars   = (const int*)d_in[0];
    const int*   lengths = (const int*)d_in[1];
    const float* forget  = (const float*)d_in[2];
    const float* W_ih_f  = (const float*)d_in[3];
    const float* W_hh_f  = (const float*)d_in[4];
    const float* b_ih_f  = (const float*)d_in[5];
    const float* b_hh_f  = (const float*)d_in[6];
    const float* W_ih_b  = (const float*)d_in[7];
    const float* W_hh_b  = (const float*)d_in[8];
    const float* b_ih_b  = (const float*)d_in[9];
    const float* b_hh_b  = (const float*)d_in[10];
    const float* W_lin   = (const float*)d_in[11];
    const float* b_lin   = (const float*)d_in[12];
    float* out = (float*)d_out;

    cudaFuncSetAttribute(xwk, cudaFuncAttributeMaxDynamicSharedMemorySize, 90 * 1024);
    cudaFuncSetAttribute(scan_kernel, cudaFuncAttributeMaxDynamicSharedMemorySize, 140 * 1024);

    wt_kernel<<<(2 * nV * nG + 255) / 256, 256>>>(W_ih_f, W_ih_b);
    xwk<<<dim3(12, 128, 2), 256, 82000>>>(chars, forget, b_ih_f, b_ih_b);
    scan_kernel<<<NBLK, 256, 135168>>>(W_hh_f, b_hh_f, W_hh_b, b_hh_b, lengths);
    out_kernel<<<dim3(2, 128), 256>>>(W_lin, b_lin, lengths, out);
}